// round 8
// baseline (speedup 1.0000x reference)
#include <cuda_runtime.h>

#define NN 100000
#define EE 1600000
#define FIN 128
#define HH 64
#define OUTF 32
#define NB_SCAN 98   // ceil(100000/1024)

// ---------------- scratch (device globals; no allocation) ----------------
// g_deg starts zero (static init); scan1_k re-zeroes after consuming.
__device__ int   g_deg[2 * NN];
__device__ float g_h[NN * HH];
__device__ float g_o[NN * HH];
__device__ float g_asrc[NN];
__device__ float g_adst[NN];
__device__ int   g_rank[2 * EE];
__device__ int   g_rowptr_loc[2 * NN];   // block-local exclusive prefix
__device__ int   g_bsum[2 * 128];
__device__ int2  g_csr[2 * EE];          // (src, __float_as_int(weight))

// ---------------- fused GEMM + attention dots + edge histogram ----------------
template <int K, bool RELU>
__global__ void gemm_hist(const float* __restrict__ X, const float* __restrict__ W,
                          float* __restrict__ Y,
                          const float* __restrict__ av_s, const float* __restrict__ av_d,
                          const int* __restrict__ e, int L) {
    __shared__ float xs[64][68];
    __shared__ float ws[64][64];
    __shared__ float redp[16][64];
    __shared__ float redd[16][64];
    int tid = threadIdx.x;

    // ---- histogram part (independent of gemm; grid-strided) ----
    {
        const int totpairs = EE / 2;
        const int stride = gridDim.x * 256;
        for (int i = blockIdx.x * 256 + tid; i < totpairs; i += stride) {
            int2 d2 = ((const int2*)(e + EE))[i];
            int2 r2;
            r2.x = atomicAdd(&g_deg[L * NN + d2.x], 1);
            r2.y = atomicAdd(&g_deg[L * NN + d2.y], 1);
            ((int2*)(g_rank + L * EE))[i] = r2;
        }
    }

    // ---- gemm part ----
    int tn = (tid & 15) * 4;
    int g  = tid >> 4;
    int tc = g * 4;
    int row0 = blockIdx.x * 64;

    float acc[4][4];
#pragma unroll
    for (int i = 0; i < 4; i++)
#pragma unroll
        for (int j = 0; j < 4; j++) acc[i][j] = 0.f;

    for (int k0 = 0; k0 < K; k0 += 64) {
        for (int idx = tid; idx < 64 * 64; idx += 256) {
            int r = idx >> 6, k = idx & 63;
            int row = row0 + r;
            float v = (row < NN) ? X[row * K + k0 + k] : 0.f;
            if (RELU) v = fmaxf(v, 0.f);
            xs[k][r] = v;
        }
        for (int idx = tid; idx < 64 * 64; idx += 256) {
            int k = idx >> 6, c = idx & 63;
            ws[k][c] = W[(k0 + k) * 64 + c];
        }
        __syncthreads();
#pragma unroll 8
        for (int kk = 0; kk < 64; ++kk) {
            float4 a = *(const float4*)&xs[kk][tn];
            float4 b = *(const float4*)&ws[kk][tc];
            acc[0][0] += a.x * b.x; acc[0][1] += a.x * b.y; acc[0][2] += a.x * b.z; acc[0][3] += a.x * b.w;
            acc[1][0] += a.y * b.x; acc[1][1] += a.y * b.y; acc[1][2] += a.y * b.z; acc[1][3] += a.y * b.w;
            acc[2][0] += a.z * b.x; acc[2][1] += a.z * b.y; acc[2][2] += a.z * b.z; acc[2][3] += a.z * b.w;
            acc[3][0] += a.w * b.x; acc[3][1] += a.w * b.y; acc[3][2] += a.w * b.z; acc[3][3] += a.w * b.w;
        }
        __syncthreads();
    }

    float as0 = av_s[tc], as1 = av_s[tc + 1], as2 = av_s[tc + 2], as3 = av_s[tc + 3];
    float ad0 = av_d[tc], ad1 = av_d[tc + 1], ad2 = av_d[tc + 2], ad3 = av_d[tc + 3];
#pragma unroll
    for (int i = 0; i < 4; i++) {
        int row = row0 + tn + i;
        if (row < NN) {
            float4 v = make_float4(acc[i][0], acc[i][1], acc[i][2], acc[i][3]);
            *(float4*)&Y[row * 64 + tc] = v;
        }
        redp[g][tn + i] = acc[i][0] * as0 + acc[i][1] * as1 + acc[i][2] * as2 + acc[i][3] * as3;
        redd[g][tn + i] = acc[i][0] * ad0 + acc[i][1] * ad1 + acc[i][2] * ad2 + acc[i][3] * ad3;
    }
    __syncthreads();
    if (tid < 64) {
        int row = row0 + tid;
        float ps = 0.f, pd = 0.f;
#pragma unroll
        for (int c = 0; c < 16; c++) { ps += redp[c][tid]; pd += redd[c][tid]; }
        if (row < NN) { g_asrc[row] = ps; g_adst[row] = pd; }
    }
}

// ---------------- scan1: block-local exclusive prefix + block sums ----------
// Also zeroes g_deg for the next call (determinism across graph replays).
__global__ void scan1_k(int L) {
    __shared__ int s[1024];
    int tid = threadIdx.x;
    int i = blockIdx.x * 1024 + tid;
    int v = (i < NN) ? g_deg[L * NN + i] : 0;
    if (i < NN) g_deg[L * NN + i] = 0;
    s[tid] = v;
    __syncthreads();
#pragma unroll
    for (int off = 1; off < 1024; off <<= 1) {
        int t = (tid >= off) ? s[tid - off] : 0;
        __syncthreads();
        s[tid] += t;
        __syncthreads();
    }
    if (i < NN) g_rowptr_loc[L * NN + i] = s[tid] - v;
    if (tid == 1023) g_bsum[L * 128 + blockIdx.x] = s[1023];
}

// helper: exclusive prefix of g_bsum into sp[128] (all 256 threads participate)
__device__ __forceinline__ void block_prefix(int* sp, int L, int tid) {
    if (tid < 128) {
        int src = tid - 1;   // shifted load => inclusive scan yields exclusive prefix
        sp[tid] = (src >= 0 && src < NB_SCAN) ? g_bsum[L * 128 + src] : 0;
    }
    __syncthreads();
#pragma unroll
    for (int off = 1; off < 128; off <<= 1) {
        int t = 0;
        if (tid < 128 && tid >= off) t = sp[tid - off];
        __syncthreads();
        if (tid < 128) sp[tid] += t;
        __syncthreads();
    }
}

// ---------------- scatter + fused softmax weights ----------------
__global__ void scatterw_k(const int* __restrict__ e, int L) {
    __shared__ int sp[128];
    int tid = threadIdx.x;
    block_prefix(sp, L, tid);

    int i = blockIdx.x * blockDim.x + tid;
    if (i < EE / 2) {
        int2 d2 = ((const int2*)(e + EE))[i];
        int2 s2 = ((const int2*)e)[i];
        int2 r2 = ((const int2*)(g_rank + L * EE))[i];
        const int* rl = g_rowptr_loc + L * NN;

        int pos0 = __ldg(&rl[d2.x]) + sp[d2.x >> 10] + r2.x;
        int pos1 = __ldg(&rl[d2.y]) + sp[d2.y >> 10] + r2.y;

        float e0 = __ldg(&g_asrc[s2.x]) + __ldg(&g_adst[d2.x]);
        float e1 = __ldg(&g_asrc[s2.y]) + __ldg(&g_adst[d2.y]);
        e0 = (e0 >= 0.f) ? e0 : 0.2f * e0;
        e1 = (e1 >= 0.f) ? e1 : 0.2f * e1;

        g_csr[L * EE + pos0] = make_int2(s2.x, __float_as_int(__expf(e0)));
        g_csr[L * EE + pos1] = make_int2(s2.y, __float_as_int(__expf(e1)));
    }
}

// ---------------- aggregate: warp per node, weights precomputed ----------
template <bool FINAL>
__global__ void agg_k(const float* __restrict__ h, const float* __restrict__ bias,
                      float* __restrict__ out, int L,
                      const float* __restrict__ Wl, const float* __restrict__ bl) {
    __shared__ int sp[128];
    __shared__ float wsh[64 * 32];
    __shared__ int2 s_e[8][32];
    int tid = threadIdx.x;
    block_prefix(sp, L, tid);
    if (FINAL) {
        for (int i = tid; i < 64 * 32; i += 256) wsh[i] = Wl[i];
        __syncthreads();
    }

    int wid = tid >> 5, lane = tid & 31;
    int node = blockIdx.x * 8 + wid;
    const int* rl = g_rowptr_loc + L * NN;
    int start = __ldg(&rl[node]) + sp[node >> 10];
    int end = (node + 1 == NN) ? EE
              : __ldg(&rl[node + 1]) + sp[(node + 1) >> 10];
    const int2* csr = g_csr + L * EE;

    int half = lane >> 4;
    int q = (lane & 15) * 4;

    float4 acc = make_float4(0.f, 0.f, 0.f, 0.f);
    float ssum = 0.f;

    for (int j0 = start; j0 < end; j0 += 32) {
        int j = j0 + lane;
        int2 p = make_int2(0, 0);
        if (j < end) {
            p = __ldg(&csr[j]);
            ssum += __int_as_float(p.y);
        }
        s_e[wid][lane] = p;
        __syncwarp();
        int cnt = min(32, end - j0);
        int jj = 0;
        for (; jj + 8 <= cnt; jj += 8) {
            int2 p0 = s_e[wid][jj + half];
            int2 p1 = s_e[wid][jj + 2 + half];
            int2 p2 = s_e[wid][jj + 4 + half];
            int2 p3 = s_e[wid][jj + 6 + half];
            float w0 = __int_as_float(p0.y), w1 = __int_as_float(p1.y);
            float w2 = __int_as_float(p2.y), w3 = __int_as_float(p3.y);
            float4 h0 = *(const float4*)(h + p0.x * 64 + q);
            float4 h1 = *(const float4*)(h + p1.x * 64 + q);
            float4 h2 = *(const float4*)(h + p2.x * 64 + q);
            float4 h3 = *(const float4*)(h + p3.x * 64 + q);
            acc.x += w0 * h0.x + w1 * h1.x + w2 * h2.x + w3 * h3.x;
            acc.y += w0 * h0.y + w1 * h1.y + w2 * h2.y + w3 * h3.y;
            acc.z += w0 * h0.z + w1 * h1.z + w2 * h2.z + w3 * h3.z;
            acc.w += w0 * h0.w + w1 * h1.w + w2 * h2.w + w3 * h3.w;
        }
        for (; jj < cnt; jj += 2) {
            int ei = jj + half;
            if (ei < cnt) {
                int2 pv = s_e[wid][ei];
                float wc = __int_as_float(pv.y);
                float4 hv = *(const float4*)(h + pv.x * 64 + q);
                acc.x += wc * hv.x; acc.y += wc * hv.y;
                acc.z += wc * hv.z; acc.w += wc * hv.w;
            }
        }
        __syncwarp();
    }

    acc.x += __shfl_xor_sync(0xffffffffu, acc.x, 16);
    acc.y += __shfl_xor_sync(0xffffffffu, acc.y, 16);
    acc.z += __shfl_xor_sync(0xffffffffu, acc.z, 16);
    acc.w += __shfl_xor_sync(0xffffffffu, acc.w, 16);
#pragma unroll
    for (int off = 16; off; off >>= 1) ssum += __shfl_xor_sync(0xffffffffu, ssum, off);
    float inv = 1.0f / (ssum + 1e-16f);

    float4 b4 = *(const float4*)(bias + q);
    float4 o;
    o.x = acc.x * inv + b4.x; o.y = acc.y * inv + b4.y;
    o.z = acc.z * inv + b4.z; o.w = acc.w * inv + b4.w;

    if (!FINAL) {
        if (half == 0) *(float4*)(out + node * 64 + q) = o;
    } else {
        float oarr[4] = {o.x, o.y, o.z, o.w};
        float accl = __ldg(&bl[lane]);
#pragma unroll
        for (int k = 0; k < 64; k++) {
            float xk = __shfl_sync(0xffffffffu, oarr[k & 3], k >> 2);
            accl += xk * wsh[k * 32 + lane];
        }
        float mx = accl;
#pragma unroll
        for (int off = 16; off; off >>= 1) mx = fmaxf(mx, __shfl_xor_sync(0xffffffffu, mx, off));
        float ex = __expf(accl - mx);
        float sum = ex;
#pragma unroll
        for (int off = 16; off; off >>= 1) sum += __shfl_xor_sync(0xffffffffu, sum, off);
        out[node * 32 + lane] = accl - mx - __logf(sum);
    }
}

// ---------------- launch: 8 kernels, fully serial, agg1 is #4 ----------------
extern "C" void kernel_launch(void* const* d_in, const int* in_sizes, int n_in,
                              void* d_out, int out_size) {
    const float* x    = (const float*)d_in[0];
    const int*   ei1  = (const int*)d_in[1];
    const int*   ei2  = (const int*)d_in[2];
    const float* W1   = (const float*)d_in[3];
    const float* as1  = (const float*)d_in[4];
    const float* ad1  = (const float*)d_in[5];
    const float* b1   = (const float*)d_in[6];
    const float* W2   = (const float*)d_in[7];
    const float* as2  = (const float*)d_in[8];
    const float* ad2  = (const float*)d_in[9];
    const float* b2   = (const float*)d_in[10];
    const float* Wlin = (const float*)d_in[11];
    const float* blin = (const float*)d_in[12];
    float* out = (float*)d_out;

    float *h, *o;
    cudaGetSymbolAddress((void**)&h, g_h);
    cudaGetSymbolAddress((void**)&o, g_o);

    const int gemm_grid = (NN + 63) / 64;   // 1563
    const int agg_grid  = NN / 8;           // 12500
    const int egrid2    = (EE / 2 + 255) / 256;

    // layer 1
    gemm_hist<FIN, false><<<gemm_grid, 256>>>(x, W1, h, as1, ad1, ei1, 0);  // #1
    scan1_k<<<NB_SCAN, 1024>>>(0);                                          // #2
    scatterw_k<<<egrid2, 256>>>(ei1, 0);                                    // #3
    agg_k<false><<<agg_grid, 256>>>(h, b1, o, 0, nullptr, nullptr);         // #4 <- ncu
    // layer 2 + final
    gemm_hist<HH, true><<<gemm_grid, 256>>>(o, W2, h, as2, ad2, ei2, 1);    // #5
    scan1_k<<<NB_SCAN, 1024>>>(1);                                          // #6
    scatterw_k<<<egrid2, 256>>>(ei2, 1);                                    // #7
    agg_k<true><<<agg_grid, 256>>>(h, b2, out, 1, Wlin, blin);              // #8
}